// round 14
// baseline (speedup 1.0000x reference)
#include <cuda_runtime.h>
#include <cuda_bf16.h>
#include <math.h>

#define DI __device__ __forceinline__

// ---------------- scratch (device globals: no allocation) ----------------
__device__ float    g_pooled[8192 * 64];
__device__ float    g_czb[8192 * 64];
__device__ float    g_tvec[200 * 64];
__device__ float    g_sr[200], g_srm1[200], g_c1[200], g_c2[200], g_sig[200];
__device__ unsigned g_k0[200], g_k1[200];

static constexpr int P = 68;   // smem pitch in floats for 64-wide tiles

// ---------------- JAX threefry2x32 (bit-exact) ----------------
DI void tf2x32(unsigned k0, unsigned k1, unsigned x0, unsigned x1,
               unsigned& o0, unsigned& o1) {
  unsigned k2 = k0 ^ k1 ^ 0x1BD11BDAu;
  x0 += k0; x1 += k1;
#define TFR(r) { x0 += x1; x1 = __funnelshift_l(x1, x1, (r)); x1 ^= x0; }
  TFR(13) TFR(15) TFR(26) TFR(6)
  x0 += k1; x1 += k2 + 1u;
  TFR(17) TFR(29) TFR(16) TFR(24)
  x0 += k2; x1 += k0 + 2u;
  TFR(13) TFR(15) TFR(26) TFR(6)
  x0 += k0; x1 += k1 + 3u;
  TFR(17) TFR(29) TFR(16) TFR(24)
  x0 += k1; x1 += k2 + 4u;
  TFR(13) TFR(15) TFR(26) TFR(6)
  x0 += k2; x1 += k0 + 5u;
#undef TFR
  o0 = x0; o1 = x1;
}

// partitionable threefry random bits for flat index i
DI unsigned jax_bits(unsigned k0, unsigned k1, unsigned i) {
  unsigned o0, o1;
  tf2x32(k0, k1, 0u, i, o0, o1);
  return o0 ^ o1;
}

// JAX normal(): uniform in [-1+2^-24, 1) then sqrt(2)*erfinv (XLA f32 poly)
DI float bits_to_normal(unsigned bits) {
  float f = __uint_as_float((bits >> 9) | 0x3f800000u) - 1.0f;   // [0,1)
  float u = fmaf(f, 2.0f, -0.99999994f);
  u = fmaxf(u, -0.99999994f);
  float w = -log1pf(-u * u);
  float ws = w - 2.5f;
  float p1 = 2.81022636e-08f;
  p1 = fmaf(p1, ws, 3.43273939e-07f);
  p1 = fmaf(p1, ws, -3.5233877e-06f);
  p1 = fmaf(p1, ws, -4.39150654e-06f);
  p1 = fmaf(p1, ws, 0.00021858087f);
  p1 = fmaf(p1, ws, -0.00125372503f);
  p1 = fmaf(p1, ws, -0.00417768164f);
  p1 = fmaf(p1, ws, 0.246640727f);
  p1 = fmaf(p1, ws, 1.50140941f);
  float wb = sqrtf(w) - 3.0f;
  float p2 = -0.000200214257f;
  p2 = fmaf(p2, wb, 0.000100950558f);
  p2 = fmaf(p2, wb, 0.00134934322f);
  p2 = fmaf(p2, wb, -0.00367342844f);
  p2 = fmaf(p2, wb, 0.00573950773f);
  p2 = fmaf(p2, wb, -0.0076224613f);
  p2 = fmaf(p2, wb, 0.00943887047f);
  p2 = fmaf(p2, wb, 1.00167406f);
  p2 = fmaf(p2, wb, 2.83297682f);
  float p = (w < 5.0f) ? p1 : p2;
  return 1.41421356f * (p * u);
}

// ---------------- setup: schedule, fold_in keys, tvec ----------------
__global__ void k_setup(const float* __restrict__ Wt,
                        const float* __restrict__ bt,
                        const float* __restrict__ bin) {
  int tid = threadIdx.x;
  __shared__ float fr[32];
  if (tid == 0) {
    double acp = 1.0;
    const double bA = 5e-4, bB = 0.1;  // scale = 1000/200 = 5
    for (int i = 0; i < 200; ++i) {
      double beta  = bA + (bB - bA) * (double)i / 199.0;
      double alpha = 1.0 - beta;
      double acp_prev = acp;
      acp *= alpha;
      g_sr[i]   = (float)sqrt(1.0 / acp);
      g_srm1[i] = (float)sqrt(1.0 / acp - 1.0);
      double pv = beta * (1.0 - acp_prev) / (1.0 - acp);
      g_sig[i]  = (i == 0) ? 0.0f : (float)sqrt(pv);
      g_c1[i]   = (float)(beta * sqrt(acp_prev) / (1.0 - acp));
      g_c2[i]   = (float)((1.0 - acp_prev) * sqrt(alpha) / (1.0 - acp));
    }
  }
  if (tid < 200) {  // fold_in(key(2)=[0,2], t)
    unsigned o0, o1;
    tf2x32(0u, 2u, 0u, (unsigned)tid, o0, o1);
    g_k0[tid] = o0; g_k1[tid] = o1;
  }
  if (tid < 32)
    fr[tid] = expf(-(logf(10000.0f) * (float)tid) / 32.0f);
  __syncthreads();
  // tvec[t][c] = b_in[c] + b_t[c] + sum_h temb_t[h] * W_t[h][c]
  for (int e = tid; e < 200 * 64; e += blockDim.x) {
    int t = e >> 6, c = e & 63;
    float acc = bin[c] + bt[c];
    for (int h = 0; h < 32; ++h) {
      float ang = (float)t * fr[h];
      float s, cz;
      sincosf(ang, &s, &cz);
      acc += cz * Wt[h * 64 + c] + s * Wt[(h + 32) * 64 + c];
    }
    g_tvec[e] = acc;
  }
}

// ---------------- pooled embedding: warp per row ----------------
__global__ void k_pool(const int* __restrict__ seq,
                       const float* __restrict__ emb) {
  int w = threadIdx.x >> 5, lane = threadIdx.x & 31;
  int row = blockIdx.x * 8 + w;
  const int* s = seq + row * 100;
  int cnt = 0;
  for (int l = lane; l < 100; l += 32) cnt += (s[l] != 0);
  for (int o = 16; o; o >>= 1) cnt += __shfl_xor_sync(0xffffffffu, cnt, o);
  float a0 = 0.f, a1 = 0.f;
  for (int l = 0; l < 100; ++l) {
    int id = __ldg(s + l);
    float2 v = *(const float2*)(emb + (size_t)id * 64 + lane * 2);
    a0 += v.x; a1 += v.y;
  }
  float sc = sqrtf((float)cnt);
  g_pooled[row * 64 + lane * 2]     = a0 / sc;
  g_pooled[row * 64 + lane * 2 + 1] = a1 / sc;
}

// ---------------- encoder MLP + cond projection: warp per row ----------------
__global__ void k_enc(const float* __restrict__ W1, const float* __restrict__ b1,
                      const float* __restrict__ W2, const float* __restrict__ b2,
                      const float* __restrict__ Wc, const float* __restrict__ bc) {
  __shared__ float sp[8][64], shh[8][256], smu[8][64];
  int w = threadIdx.x >> 5, lane = threadIdx.x & 31;
  int row = blockIdx.x * 8 + w;
  sp[w][lane * 2]     = g_pooled[row * 64 + lane * 2];
  sp[w][lane * 2 + 1] = g_pooled[row * 64 + lane * 2 + 1];
  __syncwarp();
  for (int jj = 0; jj < 8; ++jj) {
    int j = lane + 32 * jj;
    float acc = b1[j];
    for (int d = 0; d < 64; ++d) acc = fmaf(sp[w][d], W1[d * 256 + j], acc);
    shh[w][j] = fmaxf(acc, 0.0f);
  }
  __syncwarp();
  for (int cc = 0; cc < 2; ++cc) {
    int c = lane + 32 * cc;
    float acc = b2[c];
    for (int k = 0; k < 256; ++k) acc = fmaf(shh[w][k], W2[k * 128 + c], acc);
    smu[w][c] = acc;
  }
  __syncwarp();
  for (int cc = 0; cc < 2; ++cc) {
    int c = lane + 32 * cc;
    float acc = bc[c];
    for (int d = 0; d < 64; ++d) acc = fmaf(smu[w][d], Wc[d * 64 + c], acc);
    g_czb[row * 64 + c] = acc;
  }
}

// ---------------- persistent DDPM sampler: 64 rows per block ----------------
__global__ void __launch_bounds__(256, 1)
k_sample(const float* __restrict__ Win, const float* __restrict__ Wout,
         const float* __restrict__ bout, float* __restrict__ out) {
  extern __shared__ float smf[];
  float* WinS  = smf;            // 4096
  float* WoutS = smf + 4096;     // 4096
  float* tvS   = smf + 8192;     // 12800
  float* Xs    = smf + 20992;    // 64*P
  float* Hs    = smf + 20992 + 64 * P;
  __shared__ float s_sr[200], s_sm[200], s_c1[200], s_c2[200], s_sg[200];
  __shared__ unsigned s_k0[200], s_k1[200];

  int tid = threadIdx.x;
  for (int i = tid; i < 4096; i += 256) { WinS[i] = Win[i]; WoutS[i] = Wout[i]; }
  for (int i = tid; i < 12800; i += 256) tvS[i] = g_tvec[i];
  if (tid < 200) {
    s_sr[tid] = g_sr[tid]; s_sm[tid] = g_srm1[tid]; s_c1[tid] = g_c1[tid];
    s_c2[tid] = g_c2[tid]; s_sg[tid] = g_sig[tid];
    s_k0[tid] = g_k0[tid]; s_k1[tid] = g_k1[tid];
  }

  int cq = tid & 15, rb = tid >> 4;
  int c0 = cq * 4;
  int grow0 = blockIdx.x * 64 + rb;

  float czr[4][4];
  unsigned base[4];
  float4 bo = *(const float4*)(bout + c0);
#pragma unroll
  for (int i = 0; i < 4; ++i) {
    int gr = grow0 + 16 * i;
    base[i] = (unsigned)(gr * 64 + c0);
    float4 cz = *(const float4*)(g_czb + gr * 64 + c0);
    czr[i][0] = cz.x; czr[i][1] = cz.y; czr[i][2] = cz.z; czr[i][3] = cz.w;
    float4 xi;   // x_init ~ normal(key(1)=[0,1])
    xi.x = bits_to_normal(jax_bits(0u, 1u, base[i] + 0));
    xi.y = bits_to_normal(jax_bits(0u, 1u, base[i] + 1));
    xi.z = bits_to_normal(jax_bits(0u, 1u, base[i] + 2));
    xi.w = bits_to_normal(jax_bits(0u, 1u, base[i] + 3));
    *(float4*)&Xs[(rb + 16 * i) * P + c0] = xi;
  }
  __syncthreads();

  for (int t = 199; t >= 0; --t) {
    // GEMM1: H = silu(X @ W_in + tvec[t] + czb)
    float4 tv = *(float4*)&tvS[t * 64 + c0];
    float acc[4][4];
#pragma unroll
    for (int i = 0; i < 4; ++i) {
      acc[i][0] = tv.x + czr[i][0]; acc[i][1] = tv.y + czr[i][1];
      acc[i][2] = tv.z + czr[i][2]; acc[i][3] = tv.w + czr[i][3];
    }
#pragma unroll 8
    for (int k = 0; k < 64; ++k) {
      float4 wv = *(float4*)&WinS[k * 64 + c0];
#pragma unroll
      for (int i = 0; i < 4; ++i) {
        float a = Xs[(rb + 16 * i) * P + k];
        acc[i][0] = fmaf(a, wv.x, acc[i][0]);
        acc[i][1] = fmaf(a, wv.y, acc[i][1]);
        acc[i][2] = fmaf(a, wv.z, acc[i][2]);
        acc[i][3] = fmaf(a, wv.w, acc[i][3]);
      }
    }
#pragma unroll
    for (int i = 0; i < 4; ++i) {
      float4 hv;
      hv.x = acc[i][0] / (1.0f + expf(-acc[i][0]));
      hv.y = acc[i][1] / (1.0f + expf(-acc[i][1]));
      hv.z = acc[i][2] / (1.0f + expf(-acc[i][2]));
      hv.w = acc[i][3] / (1.0f + expf(-acc[i][3]));
      *(float4*)&Hs[(rb + 16 * i) * P + c0] = hv;
    }
    __syncthreads();

    // GEMM2: eps = H @ W_out + b_out
#pragma unroll
    for (int i = 0; i < 4; ++i) {
      acc[i][0] = bo.x; acc[i][1] = bo.y; acc[i][2] = bo.z; acc[i][3] = bo.w;
    }
#pragma unroll 8
    for (int k = 0; k < 64; ++k) {
      float4 wv = *(float4*)&WoutS[k * 64 + c0];
#pragma unroll
      for (int i = 0; i < 4; ++i) {
        float a = Hs[(rb + 16 * i) * P + k];
        acc[i][0] = fmaf(a, wv.x, acc[i][0]);
        acc[i][1] = fmaf(a, wv.y, acc[i][1]);
        acc[i][2] = fmaf(a, wv.z, acc[i][2]);
        acc[i][3] = fmaf(a, wv.w, acc[i][3]);
      }
    }

    // elementwise update with inline threefry noise
    float sr = s_sr[t], smm = s_sm[t], c1 = s_c1[t], c2 = s_c2[t], sg = s_sg[t];
    unsigned kk0 = s_k0[t], kk1 = s_k1[t];
#pragma unroll
    for (int i = 0; i < 4; ++i) {
      float* xp = &Xs[(rb + 16 * i) * P + c0];
      float4 xv = *(float4*)xp;
      float xo[4] = {xv.x, xv.y, xv.z, xv.w};
      float nx[4];
#pragma unroll
      for (int j = 0; j < 4; ++j) {
        float x0 = sr * xo[j] - smm * acc[i][j];
        x0 = fminf(fmaxf(x0, -1.0f), 1.0f);
        float mean = c1 * x0 + c2 * xo[j];
        float nz = bits_to_normal(jax_bits(kk0, kk1, base[i] + (unsigned)j));
        nx[j] = mean + sg * nz;
      }
      float4 w4 = {nx[0], nx[1], nx[2], nx[3]};
      *(float4*)xp = w4;
    }
    __syncthreads();
  }

#pragma unroll
  for (int i = 0; i < 4; ++i) {
    float4 v = *(float4*)&Xs[(rb + 16 * i) * P + c0];
    *(float4*)(out + (grow0 + 16 * i) * 64 + c0) = v;
  }
}

// ---------------- launch ----------------
extern "C" void kernel_launch(void* const* d_in, const int* in_sizes, int n_in,
                              void* d_out, int out_size) {
  if (n_in < 14) return;
  const int*   seq  = (const int*)d_in[0];
  const float* emb  = (const float*)d_in[1];
  const float* W1   = (const float*)d_in[2];
  const float* b1   = (const float*)d_in[3];
  const float* W2   = (const float*)d_in[4];
  const float* b2   = (const float*)d_in[5];
  const float* Win  = (const float*)d_in[6];
  const float* bin  = (const float*)d_in[7];
  const float* Wt   = (const float*)d_in[8];
  const float* bt   = (const float*)d_in[9];
  const float* Wc   = (const float*)d_in[10];
  const float* bc   = (const float*)d_in[11];
  const float* Wout = (const float*)d_in[12];
  const float* bout = (const float*)d_in[13];
  float* out = (float*)d_out;

  int B = in_sizes[0] / 100;        // 8192
  int rowBlocks = B / 8;            // warp-per-row kernels
  int sampBlocks = B / 64;          // 64 rows per sampler block

  k_setup<<<1, 256>>>(Wt, bt, bin);
  k_pool<<<rowBlocks, 256>>>(seq, emb);
  k_enc<<<rowBlocks, 256>>>(W1, b1, W2, b2, Wc, bc);

  size_t smem = (size_t)(4096 + 4096 + 12800 + 2 * 64 * P) * sizeof(float);
  cudaFuncSetAttribute(k_sample, cudaFuncAttributeMaxDynamicSharedMemorySize,
                       (int)smem);
  k_sample<<<sampBlocks, 256, smem>>>(Win, Wout, bout, out);
}

// round 15
// speedup vs baseline: 1.0398x; 1.0398x over previous
#include <cuda_runtime.h>
#include <cuda_bf16.h>
#include <math.h>

#define DI __device__ __forceinline__

// ---------------- scratch (device globals: no allocation) ----------------
__device__ float    g_pooled[8192 * 64];
__device__ float    g_czb[8192 * 64];
__device__ float    g_tvec[200 * 64];
__device__ float    g_sr[200], g_srm1[200], g_c1[200], g_c2[200], g_sig[200];
__device__ unsigned g_k0[200], g_k1[200];

static constexpr int P = 68;   // smem pitch in floats for 64-wide tiles

// ---------------- JAX threefry2x32 (bit-exact) ----------------
DI void tf2x32(unsigned k0, unsigned k1, unsigned x0, unsigned x1,
               unsigned& o0, unsigned& o1) {
  unsigned k2 = k0 ^ k1 ^ 0x1BD11BDAu;
  x0 += k0; x1 += k1;
#define TFR(r) { x0 += x1; x1 = __funnelshift_l(x1, x1, (r)); x1 ^= x0; }
  TFR(13) TFR(15) TFR(26) TFR(6)
  x0 += k1; x1 += k2 + 1u;
  TFR(17) TFR(29) TFR(16) TFR(24)
  x0 += k2; x1 += k0 + 2u;
  TFR(13) TFR(15) TFR(26) TFR(6)
  x0 += k0; x1 += k1 + 3u;
  TFR(17) TFR(29) TFR(16) TFR(24)
  x0 += k1; x1 += k2 + 4u;
  TFR(13) TFR(15) TFR(26) TFR(6)
  x0 += k2; x1 += k0 + 5u;
#undef TFR
  o0 = x0; o1 = x1;
}

// partitionable threefry random bits for flat index i
DI unsigned jax_bits(unsigned k0, unsigned k1, unsigned i) {
  unsigned o0, o1;
  tf2x32(k0, k1, 0u, i, o0, o1);
  return o0 ^ o1;
}

// JAX normal(): uniform in [-1+2^-24, 1) then sqrt(2)*erfinv (XLA f32 poly)
DI float bits_to_normal(unsigned bits) {
  float f = __uint_as_float((bits >> 9) | 0x3f800000u) - 1.0f;   // [0,1)
  float u = fmaf(f, 2.0f, -0.99999994f);
  u = fmaxf(u, -0.99999994f);
  float w = -__logf(fmaf(u, -u, 1.0f));
  float ws = w - 2.5f;
  float p1 = 2.81022636e-08f;
  p1 = fmaf(p1, ws, 3.43273939e-07f);
  p1 = fmaf(p1, ws, -3.5233877e-06f);
  p1 = fmaf(p1, ws, -4.39150654e-06f);
  p1 = fmaf(p1, ws, 0.00021858087f);
  p1 = fmaf(p1, ws, -0.00125372503f);
  p1 = fmaf(p1, ws, -0.00417768164f);
  p1 = fmaf(p1, ws, 0.246640727f);
  p1 = fmaf(p1, ws, 1.50140941f);
  float wb = sqrtf(w) - 3.0f;
  float p2 = -0.000200214257f;
  p2 = fmaf(p2, wb, 0.000100950558f);
  p2 = fmaf(p2, wb, 0.00134934322f);
  p2 = fmaf(p2, wb, -0.00367342844f);
  p2 = fmaf(p2, wb, 0.00573950773f);
  p2 = fmaf(p2, wb, -0.0076224613f);
  p2 = fmaf(p2, wb, 0.00943887047f);
  p2 = fmaf(p2, wb, 1.00167406f);
  p2 = fmaf(p2, wb, 2.83297682f);
  float p = (w < 5.0f) ? p1 : p2;
  return 1.41421356f * (p * u);
}

// ---------------- setup: schedule, fold_in keys, tvec ----------------
__global__ void k_setup(const float* __restrict__ Wt,
                        const float* __restrict__ bt,
                        const float* __restrict__ bin) {
  int tid = threadIdx.x;
  __shared__ float fr[32];
  if (tid == 0) {
    double acp = 1.0;
    const double bA = 5e-4, bB = 0.1;  // scale = 1000/200 = 5
    for (int i = 0; i < 200; ++i) {
      double beta  = bA + (bB - bA) * (double)i / 199.0;
      double alpha = 1.0 - beta;
      double acp_prev = acp;
      acp *= alpha;
      g_sr[i]   = (float)sqrt(1.0 / acp);
      g_srm1[i] = (float)sqrt(1.0 / acp - 1.0);
      double pv = beta * (1.0 - acp_prev) / (1.0 - acp);
      g_sig[i]  = (i == 0) ? 0.0f : (float)sqrt(pv);
      g_c1[i]   = (float)(beta * sqrt(acp_prev) / (1.0 - acp));
      g_c2[i]   = (float)((1.0 - acp_prev) * sqrt(alpha) / (1.0 - acp));
    }
  }
  if (tid < 200) {  // fold_in(key(2)=[0,2], t)
    unsigned o0, o1;
    tf2x32(0u, 2u, 0u, (unsigned)tid, o0, o1);
    g_k0[tid] = o0; g_k1[tid] = o1;
  }
  if (tid < 32)
    fr[tid] = expf(-(logf(10000.0f) * (float)tid) / 32.0f);
  __syncthreads();
  // tvec[t][c] = b_in[c] + b_t[c] + sum_h temb_t[h] * W_t[h][c]
  for (int e = tid; e < 200 * 64; e += blockDim.x) {
    int t = e >> 6, c = e & 63;
    float acc = bin[c] + bt[c];
    for (int h = 0; h < 32; ++h) {
      float ang = (float)t * fr[h];
      float s, cz;
      sincosf(ang, &s, &cz);
      acc += cz * Wt[h * 64 + c] + s * Wt[(h + 32) * 64 + c];
    }
    g_tvec[e] = acc;
  }
}

// ---------------- pooled embedding: warp per row ----------------
__global__ void k_pool(const int* __restrict__ seq,
                       const float* __restrict__ emb) {
  int w = threadIdx.x >> 5, lane = threadIdx.x & 31;
  int row = blockIdx.x * 8 + w;
  const int* s = seq + row * 100;
  int cnt = 0;
  for (int l = lane; l < 100; l += 32) cnt += (s[l] != 0);
  for (int o = 16; o; o >>= 1) cnt += __shfl_xor_sync(0xffffffffu, cnt, o);
  float a0 = 0.f, a1 = 0.f;
  for (int l = 0; l < 100; ++l) {
    int id = __ldg(s + l);
    float2 v = *(const float2*)(emb + (size_t)id * 64 + lane * 2);
    a0 += v.x; a1 += v.y;
  }
  float sc = sqrtf((float)cnt);
  g_pooled[row * 64 + lane * 2]     = a0 / sc;
  g_pooled[row * 64 + lane * 2 + 1] = a1 / sc;
}

// ---------------- encoder MLP + cond projection: warp per row ----------------
__global__ void k_enc(const float* __restrict__ W1, const float* __restrict__ b1,
                      const float* __restrict__ W2, const float* __restrict__ b2,
                      const float* __restrict__ Wc, const float* __restrict__ bc) {
  __shared__ float sp[8][64], shh[8][256], smu[8][64];
  int w = threadIdx.x >> 5, lane = threadIdx.x & 31;
  int row = blockIdx.x * 8 + w;
  sp[w][lane * 2]     = g_pooled[row * 64 + lane * 2];
  sp[w][lane * 2 + 1] = g_pooled[row * 64 + lane * 2 + 1];
  __syncwarp();
  for (int jj = 0; jj < 8; ++jj) {
    int j = lane + 32 * jj;
    float acc = b1[j];
    for (int d = 0; d < 64; ++d) acc = fmaf(sp[w][d], W1[d * 256 + j], acc);
    shh[w][j] = fmaxf(acc, 0.0f);
  }
  __syncwarp();
  for (int cc = 0; cc < 2; ++cc) {
    int c = lane + 32 * cc;
    float acc = b2[c];
    for (int k = 0; k < 256; ++k) acc = fmaf(shh[w][k], W2[k * 128 + c], acc);
    smu[w][c] = acc;
  }
  __syncwarp();
  for (int cc = 0; cc < 2; ++cc) {
    int c = lane + 32 * cc;
    float acc = bc[c];
    for (int d = 0; d < 64; ++d) acc = fmaf(smu[w][d], Wc[d * 64 + c], acc);
    g_czb[row * 64 + c] = acc;
  }
}

// ---------------- persistent DDPM sampler: 64 rows / block, 512 threads ----------------
__global__ void __launch_bounds__(512, 1)
k_sample(const float* __restrict__ Win, const float* __restrict__ Wout,
         const float* __restrict__ bout, float* __restrict__ out) {
  extern __shared__ float smf[];
  float* WinS  = smf;            // 4096
  float* WoutS = smf + 4096;     // 4096
  float* tvS   = smf + 8192;     // 12800
  float* Xs    = smf + 20992;    // 64*P
  float* Hs    = smf + 20992 + 64 * P;
  __shared__ float s_sr[200], s_sm[200], s_c1[200], s_c2[200], s_sg[200];
  __shared__ unsigned s_k0[200], s_k1[200];

  int tid = threadIdx.x;
  for (int i = tid; i < 4096; i += 512) { WinS[i] = Win[i]; WoutS[i] = Wout[i]; }
  for (int i = tid; i < 12800; i += 512) tvS[i] = g_tvec[i];
  if (tid < 200) {
    s_sr[tid] = g_sr[tid]; s_sm[tid] = g_srm1[tid]; s_c1[tid] = g_c1[tid];
    s_c2[tid] = g_c2[tid]; s_sg[tid] = g_sig[tid];
    s_k0[tid] = g_k0[tid]; s_k1[tid] = g_k1[tid];
  }

  int cq = tid & 15, rw = tid >> 4;   // rw in 0..31
  int c0 = cq * 4;
  int r0 = rw, r1 = rw + 32;
  int g0 = blockIdx.x * 64 + r0;
  int g1 = g0 + 32;
  unsigned b0 = (unsigned)(g0 * 64 + c0);
  unsigned b1 = (unsigned)(g1 * 64 + c0);

  float4 cz0 = *(const float4*)(g_czb + g0 * 64 + c0);
  float4 cz1 = *(const float4*)(g_czb + g1 * 64 + c0);
  float4 bo  = *(const float4*)(bout + c0);

  // x_init ~ normal(key(1) = [0,1])
  {
    float4 xi0, xi1;
    xi0.x = bits_to_normal(jax_bits(0u, 1u, b0 + 0));
    xi0.y = bits_to_normal(jax_bits(0u, 1u, b0 + 1));
    xi0.z = bits_to_normal(jax_bits(0u, 1u, b0 + 2));
    xi0.w = bits_to_normal(jax_bits(0u, 1u, b0 + 3));
    xi1.x = bits_to_normal(jax_bits(0u, 1u, b1 + 0));
    xi1.y = bits_to_normal(jax_bits(0u, 1u, b1 + 1));
    xi1.z = bits_to_normal(jax_bits(0u, 1u, b1 + 2));
    xi1.w = bits_to_normal(jax_bits(0u, 1u, b1 + 3));
    *(float4*)&Xs[r0 * P + c0] = xi0;
    *(float4*)&Xs[r1 * P + c0] = xi1;
  }
  __syncthreads();

  for (int t = 199; t >= 0; --t) {
    float sr = s_sr[t], smm = s_sm[t], c1c = s_c1[t], c2c = s_c2[t], sg = s_sg[t];
    unsigned kk0 = s_k0[t], kk1 = s_k1[t];

    // ---- GEMM1: H = silu(X @ W_in + tvec[t] + czb) ----
    float4 tv = *(float4*)&tvS[t * 64 + c0];
    float acc0[4], acc1[4];
    acc0[0] = tv.x + cz0.x; acc0[1] = tv.y + cz0.y;
    acc0[2] = tv.z + cz0.z; acc0[3] = tv.w + cz0.w;
    acc1[0] = tv.x + cz1.x; acc1[1] = tv.y + cz1.y;
    acc1[2] = tv.z + cz1.z; acc1[3] = tv.w + cz1.w;
#pragma unroll
    for (int k4 = 0; k4 < 64; k4 += 4) {
      float4 A0 = *(float4*)&Xs[r0 * P + k4];
      float4 A1 = *(float4*)&Xs[r1 * P + k4];
      float a0v[4] = {A0.x, A0.y, A0.z, A0.w};
      float a1v[4] = {A1.x, A1.y, A1.z, A1.w};
#pragma unroll
      for (int kk = 0; kk < 4; ++kk) {
        float4 wv = *(float4*)&WinS[(k4 + kk) * 64 + c0];
        acc0[0] = fmaf(a0v[kk], wv.x, acc0[0]);
        acc0[1] = fmaf(a0v[kk], wv.y, acc0[1]);
        acc0[2] = fmaf(a0v[kk], wv.z, acc0[2]);
        acc0[3] = fmaf(a0v[kk], wv.w, acc0[3]);
        acc1[0] = fmaf(a1v[kk], wv.x, acc1[0]);
        acc1[1] = fmaf(a1v[kk], wv.y, acc1[1]);
        acc1[2] = fmaf(a1v[kk], wv.z, acc1[2]);
        acc1[3] = fmaf(a1v[kk], wv.w, acc1[3]);
      }
    }
    {
      float4 h0, h1;
      h0.x = __fdividef(acc0[0], 1.0f + __expf(-acc0[0]));
      h0.y = __fdividef(acc0[1], 1.0f + __expf(-acc0[1]));
      h0.z = __fdividef(acc0[2], 1.0f + __expf(-acc0[2]));
      h0.w = __fdividef(acc0[3], 1.0f + __expf(-acc0[3]));
      h1.x = __fdividef(acc1[0], 1.0f + __expf(-acc1[0]));
      h1.y = __fdividef(acc1[1], 1.0f + __expf(-acc1[1]));
      h1.z = __fdividef(acc1[2], 1.0f + __expf(-acc1[2]));
      h1.w = __fdividef(acc1[3], 1.0f + __expf(-acc1[3]));
      *(float4*)&Hs[r0 * P + c0] = h0;
      *(float4*)&Hs[r1 * P + c0] = h1;
    }

    // ---- noise (independent of smem state: overlap with barrier/GEMM2) ----
    float nz[8];
#pragma unroll
    for (int j = 0; j < 4; ++j) nz[j]     = bits_to_normal(jax_bits(kk0, kk1, b0 + (unsigned)j));
#pragma unroll
    for (int j = 0; j < 4; ++j) nz[4 + j] = bits_to_normal(jax_bits(kk0, kk1, b1 + (unsigned)j));

    __syncthreads();

    // ---- GEMM2: eps = H @ W_out + b_out ----
    float e0[4], e1[4];
    e0[0] = bo.x; e0[1] = bo.y; e0[2] = bo.z; e0[3] = bo.w;
    e1[0] = bo.x; e1[1] = bo.y; e1[2] = bo.z; e1[3] = bo.w;
#pragma unroll
    for (int k4 = 0; k4 < 64; k4 += 4) {
      float4 A0 = *(float4*)&Hs[r0 * P + k4];
      float4 A1 = *(float4*)&Hs[r1 * P + k4];
      float a0v[4] = {A0.x, A0.y, A0.z, A0.w};
      float a1v[4] = {A1.x, A1.y, A1.z, A1.w};
#pragma unroll
      for (int kk = 0; kk < 4; ++kk) {
        float4 wv = *(float4*)&WoutS[(k4 + kk) * 64 + c0];
        e0[0] = fmaf(a0v[kk], wv.x, e0[0]);
        e0[1] = fmaf(a0v[kk], wv.y, e0[1]);
        e0[2] = fmaf(a0v[kk], wv.z, e0[2]);
        e0[3] = fmaf(a0v[kk], wv.w, e0[3]);
        e1[0] = fmaf(a1v[kk], wv.x, e1[0]);
        e1[1] = fmaf(a1v[kk], wv.y, e1[1]);
        e1[2] = fmaf(a1v[kk], wv.z, e1[2]);
        e1[3] = fmaf(a1v[kk], wv.w, e1[3]);
      }
    }

    // ---- elementwise update ----
    {
      float4 xv0 = *(float4*)&Xs[r0 * P + c0];
      float4 xv1 = *(float4*)&Xs[r1 * P + c0];
      float xo0[4] = {xv0.x, xv0.y, xv0.z, xv0.w};
      float xo1[4] = {xv1.x, xv1.y, xv1.z, xv1.w};
      float n0[4], n1[4];
#pragma unroll
      for (int j = 0; j < 4; ++j) {
        float x0 = sr * xo0[j] - smm * e0[j];
        x0 = fminf(fmaxf(x0, -1.0f), 1.0f);
        n0[j] = c1c * x0 + c2c * xo0[j] + sg * nz[j];
      }
#pragma unroll
      for (int j = 0; j < 4; ++j) {
        float x0 = sr * xo1[j] - smm * e1[j];
        x0 = fminf(fmaxf(x0, -1.0f), 1.0f);
        n1[j] = c1c * x0 + c2c * xo1[j] + sg * nz[4 + j];
      }
      float4 w0 = {n0[0], n0[1], n0[2], n0[3]};
      float4 w1 = {n1[0], n1[1], n1[2], n1[3]};
      *(float4*)&Xs[r0 * P + c0] = w0;
      *(float4*)&Xs[r1 * P + c0] = w1;
    }
    __syncthreads();
  }

  {
    float4 v0 = *(float4*)&Xs[r0 * P + c0];
    float4 v1 = *(float4*)&Xs[r1 * P + c0];
    *(float4*)(out + g0 * 64 + c0) = v0;
    *(float4*)(out + g1 * 64 + c0) = v1;
  }
}

// ---------------- launch ----------------
extern "C" void kernel_launch(void* const* d_in, const int* in_sizes, int n_in,
                              void* d_out, int out_size) {
  if (n_in < 14) return;
  const int*   seq  = (const int*)d_in[0];
  const float* emb  = (const float*)d_in[1];
  const float* W1   = (const float*)d_in[2];
  const float* b1   = (const float*)d_in[3];
  const float* W2   = (const float*)d_in[4];
  const float* b2   = (const float*)d_in[5];
  const float* Win  = (const float*)d_in[6];
  const float* bin  = (const float*)d_in[7];
  const float* Wt   = (const float*)d_in[8];
  const float* bt   = (const float*)d_in[9];
  const float* Wc   = (const float*)d_in[10];
  const float* bc   = (const float*)d_in[11];
  const float* Wout = (const float*)d_in[12];
  const float* bout = (const float*)d_in[13];
  float* out = (float*)d_out;

  int B = in_sizes[0] / 100;        // 8192
  int rowBlocks = B / 8;            // warp-per-row kernels
  int sampBlocks = B / 64;          // 64 rows per sampler block

  k_setup<<<1, 256>>>(Wt, bt, bin);
  k_pool<<<rowBlocks, 256>>>(seq, emb);
  k_enc<<<rowBlocks, 256>>>(W1, b1, W2, b2, Wc, bc);

  size_t smem = (size_t)(4096 + 4096 + 12800 + 2 * 64 * P) * sizeof(float);
  cudaFuncSetAttribute(k_sample, cudaFuncAttributeMaxDynamicSharedMemorySize,
                       (int)smem);
  k_sample<<<sampBlocks, 512, smem>>>(Win, Wout, bout, out);
}

// round 16
// speedup vs baseline: 1.1508x; 1.1067x over previous
#include <cuda_runtime.h>
#include <cuda_bf16.h>
#include <math.h>

#define DI __device__ __forceinline__

// ---------------- scratch (device globals: no allocation) ----------------
__device__ float    g_pooled[8192 * 64];
__device__ float    g_czb[8192 * 64];
__device__ float    g_tvec[200 * 64];
__device__ float    g_sr[200], g_srm1[200], g_c1[200], g_c2[200], g_sig[200];
__device__ unsigned g_k0[200], g_k1[200];

static constexpr int P = 68;   // smem pitch in floats for 64-wide tiles

// ---------------- JAX threefry2x32 (bit-exact) ----------------
DI void tf2x32(unsigned k0, unsigned k1, unsigned x0, unsigned x1,
               unsigned& o0, unsigned& o1) {
  unsigned k2 = k0 ^ k1 ^ 0x1BD11BDAu;
  x0 += k0; x1 += k1;
#define TFR(r) { x0 += x1; x1 = __funnelshift_l(x1, x1, (r)); x1 ^= x0; }
  TFR(13) TFR(15) TFR(26) TFR(6)
  x0 += k1; x1 += k2 + 1u;
  TFR(17) TFR(29) TFR(16) TFR(24)
  x0 += k2; x1 += k0 + 2u;
  TFR(13) TFR(15) TFR(26) TFR(6)
  x0 += k0; x1 += k1 + 3u;
  TFR(17) TFR(29) TFR(16) TFR(24)
  x0 += k1; x1 += k2 + 4u;
  TFR(13) TFR(15) TFR(26) TFR(6)
  x0 += k2; x1 += k0 + 5u;
#undef TFR
  o0 = x0; o1 = x1;
}

// partitionable threefry random bits for flat index i
DI unsigned jax_bits(unsigned k0, unsigned k1, unsigned i) {
  unsigned o0, o1;
  tf2x32(k0, k1, 0u, i, o0, o1);
  return o0 ^ o1;
}

// JAX normal(): uniform in [-1+2^-24, 1) then sqrt(2)*erfinv (XLA f32 poly)
DI float bits_to_normal(unsigned bits) {
  float f = __uint_as_float((bits >> 9) | 0x3f800000u) - 1.0f;   // [0,1)
  float u = fmaf(f, 2.0f, -0.99999994f);
  u = fmaxf(u, -0.99999994f);
  float w = -__logf(fmaf(u, -u, 1.0f));
  float ws = w - 2.5f;
  float p1 = 2.81022636e-08f;
  p1 = fmaf(p1, ws, 3.43273939e-07f);
  p1 = fmaf(p1, ws, -3.5233877e-06f);
  p1 = fmaf(p1, ws, -4.39150654e-06f);
  p1 = fmaf(p1, ws, 0.00021858087f);
  p1 = fmaf(p1, ws, -0.00125372503f);
  p1 = fmaf(p1, ws, -0.00417768164f);
  p1 = fmaf(p1, ws, 0.246640727f);
  p1 = fmaf(p1, ws, 1.50140941f);
  float wb = sqrtf(w) - 3.0f;
  float p2 = -0.000200214257f;
  p2 = fmaf(p2, wb, 0.000100950558f);
  p2 = fmaf(p2, wb, 0.00134934322f);
  p2 = fmaf(p2, wb, -0.00367342844f);
  p2 = fmaf(p2, wb, 0.00573950773f);
  p2 = fmaf(p2, wb, -0.0076224613f);
  p2 = fmaf(p2, wb, 0.00943887047f);
  p2 = fmaf(p2, wb, 1.00167406f);
  p2 = fmaf(p2, wb, 2.83297682f);
  float p = (w < 5.0f) ? p1 : p2;
  return 1.41421356f * (p * u);
}

// ---------------- setup: schedule, fold_in keys, tvec ----------------
__global__ void k_setup(const float* __restrict__ Wt,
                        const float* __restrict__ bt,
                        const float* __restrict__ bin) {
  int tid = threadIdx.x;
  __shared__ float fr[32];
  if (tid == 0) {
    double acp = 1.0;
    const double bA = 5e-4, bB = 0.1;  // scale = 1000/200 = 5
    for (int i = 0; i < 200; ++i) {
      double beta  = bA + (bB - bA) * (double)i / 199.0;
      double alpha = 1.0 - beta;
      double acp_prev = acp;
      acp *= alpha;
      g_sr[i]   = (float)sqrt(1.0 / acp);
      g_srm1[i] = (float)sqrt(1.0 / acp - 1.0);
      double pv = beta * (1.0 - acp_prev) / (1.0 - acp);
      g_sig[i]  = (i == 0) ? 0.0f : (float)sqrt(pv);
      g_c1[i]   = (float)(beta * sqrt(acp_prev) / (1.0 - acp));
      g_c2[i]   = (float)((1.0 - acp_prev) * sqrt(alpha) / (1.0 - acp));
    }
  }
  if (tid < 200) {  // fold_in(key(2)=[0,2], t)
    unsigned o0, o1;
    tf2x32(0u, 2u, 0u, (unsigned)tid, o0, o1);
    g_k0[tid] = o0; g_k1[tid] = o1;
  }
  if (tid < 32)
    fr[tid] = expf(-(logf(10000.0f) * (float)tid) / 32.0f);
  __syncthreads();
  // tvec[t][c] = b_in[c] + b_t[c] + sum_h temb_t[h] * W_t[h][c]
  for (int e = tid; e < 200 * 64; e += blockDim.x) {
    int t = e >> 6, c = e & 63;
    float acc = bin[c] + bt[c];
    for (int h = 0; h < 32; ++h) {
      float ang = (float)t * fr[h];
      float s, cz;
      sincosf(ang, &s, &cz);
      acc += cz * Wt[h * 64 + c] + s * Wt[(h + 32) * 64 + c];
    }
    g_tvec[e] = acc;
  }
}

// ---------------- pooled embedding: warp per row ----------------
__global__ void k_pool(const int* __restrict__ seq,
                       const float* __restrict__ emb) {
  int w = threadIdx.x >> 5, lane = threadIdx.x & 31;
  int row = blockIdx.x * 8 + w;
  const int* s = seq + row * 100;
  int cnt = 0;
  for (int l = lane; l < 100; l += 32) cnt += (s[l] != 0);
  for (int o = 16; o; o >>= 1) cnt += __shfl_xor_sync(0xffffffffu, cnt, o);
  float a0 = 0.f, a1 = 0.f;
  for (int l = 0; l < 100; ++l) {
    int id = __ldg(s + l);
    float2 v = *(const float2*)(emb + (size_t)id * 64 + lane * 2);
    a0 += v.x; a1 += v.y;
  }
  float sc = sqrtf((float)cnt);
  g_pooled[row * 64 + lane * 2]     = a0 / sc;
  g_pooled[row * 64 + lane * 2 + 1] = a1 / sc;
}

// ---------------- encoder MLP + cond projection: warp per row ----------------
__global__ void k_enc(const float* __restrict__ W1, const float* __restrict__ b1,
                      const float* __restrict__ W2, const float* __restrict__ b2,
                      const float* __restrict__ Wc, const float* __restrict__ bc) {
  __shared__ float sp[8][64], shh[8][256], smu[8][64];
  int w = threadIdx.x >> 5, lane = threadIdx.x & 31;
  int row = blockIdx.x * 8 + w;
  sp[w][lane * 2]     = g_pooled[row * 64 + lane * 2];
  sp[w][lane * 2 + 1] = g_pooled[row * 64 + lane * 2 + 1];
  __syncwarp();
  for (int jj = 0; jj < 8; ++jj) {
    int j = lane + 32 * jj;
    float acc = b1[j];
    for (int d = 0; d < 64; ++d) acc = fmaf(sp[w][d], W1[d * 256 + j], acc);
    shh[w][j] = fmaxf(acc, 0.0f);
  }
  __syncwarp();
  for (int cc = 0; cc < 2; ++cc) {
    int c = lane + 32 * cc;
    float acc = b2[c];
    for (int k = 0; k < 256; ++k) acc = fmaf(shh[w][k], W2[k * 128 + c], acc);
    smu[w][c] = acc;
  }
  __syncwarp();
  for (int cc = 0; cc < 2; ++cc) {
    int c = lane + 32 * cc;
    float acc = bc[c];
    for (int d = 0; d < 64; ++d) acc = fmaf(smu[w][d], Wc[d * 64 + c], acc);
    g_czb[row * 64 + c] = acc;
  }
}

// ---------------- persistent DDPM sampler: 64 rows / block, 512 threads ----------------
// Warp-local dataflow: warp w exclusively owns X/H rows {2w, 2w+1, 2w+32, 2w+33}
// (thread (rw,cq): rows rw and rw+32; lanes of warp w have rw in {2w, 2w+1}).
// GEMM2 reads only H rows its own warp wrote; the X update feeds only its own
// warp's GEMM1 next step. So the 200-step loop needs only __syncwarp() —
// no block barriers, warps drift freely, ALU (threefry) and FMA (GEMM)
// phases of different warps overlap.
__global__ void __launch_bounds__(512, 1)
k_sample(const float* __restrict__ Win, const float* __restrict__ Wout,
         const float* __restrict__ bout, float* __restrict__ out) {
  extern __shared__ float smf[];
  float* WinS  = smf;            // 4096
  float* WoutS = smf + 4096;     // 4096
  float* tvS   = smf + 8192;     // 12800
  float* Xs    = smf + 20992;    // 64*P
  float* Hs    = smf + 20992 + 64 * P;
  __shared__ float s_sr[200], s_sm[200], s_c1[200], s_c2[200], s_sg[200];
  __shared__ unsigned s_k0[200], s_k1[200];

  int tid = threadIdx.x;
  for (int i = tid; i < 4096; i += 512) { WinS[i] = Win[i]; WoutS[i] = Wout[i]; }
  for (int i = tid; i < 12800; i += 512) tvS[i] = g_tvec[i];
  if (tid < 200) {
    s_sr[tid] = g_sr[tid]; s_sm[tid] = g_srm1[tid]; s_c1[tid] = g_c1[tid];
    s_c2[tid] = g_c2[tid]; s_sg[tid] = g_sig[tid];
    s_k0[tid] = g_k0[tid]; s_k1[tid] = g_k1[tid];
  }

  int cq = tid & 15, rw = tid >> 4;   // rw in 0..31
  int c0 = cq * 4;
  int r0 = rw, r1 = rw + 32;
  int g0 = blockIdx.x * 64 + r0;
  int g1 = g0 + 32;
  unsigned b0 = (unsigned)(g0 * 64 + c0);
  unsigned b1 = (unsigned)(g1 * 64 + c0);

  float4 cz0 = *(const float4*)(g_czb + g0 * 64 + c0);
  float4 cz1 = *(const float4*)(g_czb + g1 * 64 + c0);
  float4 bo  = *(const float4*)(bout + c0);

  // x_init ~ normal(key(1) = [0,1])
  {
    float4 xi0, xi1;
    xi0.x = bits_to_normal(jax_bits(0u, 1u, b0 + 0));
    xi0.y = bits_to_normal(jax_bits(0u, 1u, b0 + 1));
    xi0.z = bits_to_normal(jax_bits(0u, 1u, b0 + 2));
    xi0.w = bits_to_normal(jax_bits(0u, 1u, b0 + 3));
    xi1.x = bits_to_normal(jax_bits(0u, 1u, b1 + 0));
    xi1.y = bits_to_normal(jax_bits(0u, 1u, b1 + 1));
    xi1.z = bits_to_normal(jax_bits(0u, 1u, b1 + 2));
    xi1.w = bits_to_normal(jax_bits(0u, 1u, b1 + 3));
    *(float4*)&Xs[r0 * P + c0] = xi0;
    *(float4*)&Xs[r1 * P + c0] = xi1;
  }
  __syncthreads();   // weights/tvec visible to all; X rows only need own warp

  for (int t = 199; t >= 0; --t) {
    float sr = s_sr[t], smm = s_sm[t], c1c = s_c1[t], c2c = s_c2[t], sg = s_sg[t];
    unsigned kk0 = s_k0[t], kk1 = s_k1[t];

    // ---- GEMM1: H = silu(X @ W_in + tvec[t] + czb) ----
    float4 tv = *(float4*)&tvS[t * 64 + c0];
    float acc0[4], acc1[4];
    acc0[0] = tv.x + cz0.x; acc0[1] = tv.y + cz0.y;
    acc0[2] = tv.z + cz0.z; acc0[3] = tv.w + cz0.w;
    acc1[0] = tv.x + cz1.x; acc1[1] = tv.y + cz1.y;
    acc1[2] = tv.z + cz1.z; acc1[3] = tv.w + cz1.w;
#pragma unroll
    for (int k4 = 0; k4 < 64; k4 += 4) {
      float4 A0 = *(float4*)&Xs[r0 * P + k4];
      float4 A1 = *(float4*)&Xs[r1 * P + k4];
      float a0v[4] = {A0.x, A0.y, A0.z, A0.w};
      float a1v[4] = {A1.x, A1.y, A1.z, A1.w};
#pragma unroll
      for (int kk = 0; kk < 4; ++kk) {
        float4 wv = *(float4*)&WinS[(k4 + kk) * 64 + c0];
        acc0[0] = fmaf(a0v[kk], wv.x, acc0[0]);
        acc0[1] = fmaf(a0v[kk], wv.y, acc0[1]);
        acc0[2] = fmaf(a0v[kk], wv.z, acc0[2]);
        acc0[3] = fmaf(a0v[kk], wv.w, acc0[3]);
        acc1[0] = fmaf(a1v[kk], wv.x, acc1[0]);
        acc1[1] = fmaf(a1v[kk], wv.y, acc1[1]);
        acc1[2] = fmaf(a1v[kk], wv.z, acc1[2]);
        acc1[3] = fmaf(a1v[kk], wv.w, acc1[3]);
      }
    }
    {
      float4 h0, h1;
      h0.x = __fdividef(acc0[0], 1.0f + __expf(-acc0[0]));
      h0.y = __fdividef(acc0[1], 1.0f + __expf(-acc0[1]));
      h0.z = __fdividef(acc0[2], 1.0f + __expf(-acc0[2]));
      h0.w = __fdividef(acc0[3], 1.0f + __expf(-acc0[3]));
      h1.x = __fdividef(acc1[0], 1.0f + __expf(-acc1[0]));
      h1.y = __fdividef(acc1[1], 1.0f + __expf(-acc1[1]));
      h1.z = __fdividef(acc1[2], 1.0f + __expf(-acc1[2]));
      h1.w = __fdividef(acc1[3], 1.0f + __expf(-acc1[3]));
      *(float4*)&Hs[r0 * P + c0] = h0;
      *(float4*)&Hs[r1 * P + c0] = h1;
    }
    __syncwarp();   // H rows are warp-local: warp-level visibility suffices

    // ---- noise (independent ALU stream; interleaves with GEMM2 FMAs) ----
    float nz[8];
#pragma unroll
    for (int j = 0; j < 4; ++j) nz[j]     = bits_to_normal(jax_bits(kk0, kk1, b0 + (unsigned)j));
#pragma unroll
    for (int j = 0; j < 4; ++j) nz[4 + j] = bits_to_normal(jax_bits(kk0, kk1, b1 + (unsigned)j));

    // ---- GEMM2: eps = H @ W_out + b_out ----
    float e0[4], e1[4];
    e0[0] = bo.x; e0[1] = bo.y; e0[2] = bo.z; e0[3] = bo.w;
    e1[0] = bo.x; e1[1] = bo.y; e1[2] = bo.z; e1[3] = bo.w;
#pragma unroll
    for (int k4 = 0; k4 < 64; k4 += 4) {
      float4 A0 = *(float4*)&Hs[r0 * P + k4];
      float4 A1 = *(float4*)&Hs[r1 * P + k4];
      float a0v[4] = {A0.x, A0.y, A0.z, A0.w};
      float a1v[4] = {A1.x, A1.y, A1.z, A1.w};
#pragma unroll
      for (int kk = 0; kk < 4; ++kk) {
        float4 wv = *(float4*)&WoutS[(k4 + kk) * 64 + c0];
        e0[0] = fmaf(a0v[kk], wv.x, e0[0]);
        e0[1] = fmaf(a0v[kk], wv.y, e0[1]);
        e0[2] = fmaf(a0v[kk], wv.z, e0[2]);
        e0[3] = fmaf(a0v[kk], wv.w, e0[3]);
        e1[0] = fmaf(a1v[kk], wv.x, e1[0]);
        e1[1] = fmaf(a1v[kk], wv.y, e1[1]);
        e1[2] = fmaf(a1v[kk], wv.z, e1[2]);
        e1[3] = fmaf(a1v[kk], wv.w, e1[3]);
      }
    }

    // ---- elementwise update ----
    {
      float4 xv0 = *(float4*)&Xs[r0 * P + c0];
      float4 xv1 = *(float4*)&Xs[r1 * P + c0];
      float xo0[4] = {xv0.x, xv0.y, xv0.z, xv0.w};
      float xo1[4] = {xv1.x, xv1.y, xv1.z, xv1.w};
      float n0[4], n1[4];
#pragma unroll
      for (int j = 0; j < 4; ++j) {
        float x0 = sr * xo0[j] - smm * e0[j];
        x0 = fminf(fmaxf(x0, -1.0f), 1.0f);
        n0[j] = c1c * x0 + c2c * xo0[j] + sg * nz[j];
      }
#pragma unroll
      for (int j = 0; j < 4; ++j) {
        float x0 = sr * xo1[j] - smm * e1[j];
        x0 = fminf(fmaxf(x0, -1.0f), 1.0f);
        n1[j] = c1c * x0 + c2c * xo1[j] + sg * nz[4 + j];
      }
      float4 w0 = {n0[0], n0[1], n0[2], n0[3]};
      float4 w1 = {n1[0], n1[1], n1[2], n1[3]};
      *(float4*)&Xs[r0 * P + c0] = w0;
      *(float4*)&Xs[r1 * P + c0] = w1;
    }
    __syncwarp();   // X rows are warp-local too
  }

  {
    float4 v0 = *(float4*)&Xs[r0 * P + c0];
    float4 v1 = *(float4*)&Xs[r1 * P + c0];
    *(float4*)(out + g0 * 64 + c0) = v0;
    *(float4*)(out + g1 * 64 + c0) = v1;
  }
}

// ---------------- launch ----------------
extern "C" void kernel_launch(void* const* d_in, const int* in_sizes, int n_in,
                              void* d_out, int out_size) {
  if (n_in < 14) return;
  const int*   seq  = (const int*)d_in[0];
  const float* emb  = (const float*)d_in[1];
  const float* W1   = (const float*)d_in[2];
  const float* b1   = (const float*)d_in[3];
  const float* W2   = (const float*)d_in[4];
  const float* b2   = (const float*)d_in[5];
  const float* Win  = (const float*)d_in[6];
  const float* bin  = (const float*)d_in[7];
  const float* Wt   = (const float*)d_in[8];
  const float* bt   = (const float*)d_in[9];
  const float* Wc   = (const float*)d_in[10];
  const float* bc   = (const float*)d_in[11];
  const float* Wout = (const float*)d_in[12];
  const float* bout = (const float*)d_in[13];
  float* out = (float*)d_out;

  int B = in_sizes[0] / 100;        // 8192
  int rowBlocks = B / 8;            // warp-per-row kernels
  int sampBlocks = B / 64;          // 64 rows per sampler block

  k_setup<<<1, 256>>>(Wt, bt, bin);
  k_pool<<<rowBlocks, 256>>>(seq, emb);
  k_enc<<<rowBlocks, 256>>>(W1, b1, W2, b2, Wc, bc);

  size_t smem = (size_t)(4096 + 4096 + 12800 + 2 * 64 * P) * sizeof(float);
  cudaFuncSetAttribute(k_sample, cudaFuncAttributeMaxDynamicSharedMemorySize,
                       (int)smem);
  k_sample<<<sampBlocks, 512, smem>>>(Win, Wout, bout, out);
}